// round 6
// baseline (speedup 1.0000x reference)
#include <cuda_runtime.h>

#define F_IN  14
#define HEADS 8
#define DIM   8
#define F1    64          // HEADS*DIM
#define NEG   0.2f
#define MAXN  100000
#define MAXE  1600000

// ------------------------- scratch (device globals; no allocs) -------------
__device__ float g_h1  [MAXN * F1];     // layer1 linear output [N,64]
__device__ float g_hL2 [MAXN * F1];     // layer1 final output (ELU'd) = layer2 input
__device__ float g_as1 [MAXN * HEADS];
__device__ float g_ad1 [MAXN * HEADS];
__device__ float g_h2  [MAXN * DIM];    // layer2 linear output [N,8]
__device__ float g_as2 [MAXN];
__device__ float g_ad2 [MAXN];
__device__ int   g_src [MAXE];
__device__ int   g_dst [MAXE];
__device__ int   g_ssrc[MAXE];          // src ids sorted by dst (CSR col idx)
__device__ int   g_cnt [MAXN];          // in-degree histogram
__device__ int   g_off [MAXN + 1];      // CSR row offsets
__device__ int   g_cur [MAXN];          // scatter cursors
__device__ int   g_is64;

// ------------------------- helpers ----------------------------------------
__device__ __forceinline__ float lrelu(float x) { return x > 0.f ? x : NEG * x; }

// ------------------------- edge dtype detect -------------------------------
__global__ void k_detect(const unsigned long long* p) {
    if (threadIdx.x == 0) {
        int is64 = 1;
        for (int i = 0; i < 64; i++)
            if (p[i] >> 32) { is64 = 0; break; }
        g_is64 = is64;
    }
}

__global__ void k_zero(int n) {
    int i = blockIdx.x * blockDim.x + threadIdx.x;
    if (i < n) g_cnt[i] = 0;
}

// convert indices to int32 + build dst histogram
__global__ void k_convert(const void* ei, int e) {
    int i = blockIdx.x * blockDim.x + threadIdx.x;
    if (i >= e) return;
    int s, d;
    if (g_is64) {
        const long long* p = (const long long*)ei;
        s = (int)p[i]; d = (int)p[e + i];
    } else {
        const int* p = (const int*)ei;
        s = p[i]; d = p[e + i];
    }
    g_src[i] = s;
    g_dst[i] = d;
    atomicAdd(&g_cnt[d], 1);
}

// single-block exclusive scan of g_cnt -> g_off / g_cur
__global__ void __launch_bounds__(1024) k_scan(int n, int e) {
    __shared__ int sp[1024];
    int t = threadIdx.x;
    int chunk = (n + 1023) >> 10;
    int beg = t * chunk, end = min(beg + chunk, n);
    int sum = 0;
    for (int i = beg; i < end; i++) sum += g_cnt[i];
    sp[t] = sum;
    __syncthreads();
    for (int off = 1; off < 1024; off <<= 1) {
        int v = (t >= off) ? sp[t - off] : 0;
        __syncthreads();
        sp[t] += v;
        __syncthreads();
    }
    int run = (t == 0) ? 0 : sp[t - 1];
    for (int i = beg; i < end; i++) {
        g_off[i] = run;
        g_cur[i] = run;
        run += g_cnt[i];
    }
    if (t == 1023) g_off[n] = e;
}

__global__ void k_scatter(int e) {
    int i = blockIdx.x * blockDim.x + threadIdx.x;
    if (i >= e) return;
    int d = g_dst[i];
    int pos = atomicAdd(&g_cur[d], 1);
    g_ssrc[pos] = g_src[i];
}

// ------------------------- layer 1: fused gemm + logits --------------------
// 64 threads per node (block = 4 nodes); 8-lane butterflies reduce per-head logits.
__global__ void __launch_bounds__(256) k_l1(const float* __restrict__ x,
                                            const float* __restrict__ W1,
                                            const float* __restrict__ asrc,
                                            const float* __restrict__ adst, int n) {
    __shared__ float sW[F_IN * F1];
    __shared__ float sS[F1], sD[F1];
    int tid = threadIdx.x;
    for (int i = tid; i < F_IN * F1; i += 256) sW[i] = W1[i];
    if (tid < F1) { sS[tid] = asrc[tid]; sD[tid] = adst[tid]; }
    __syncthreads();

    int node = blockIdx.x * 4 + (tid >> 6);
    int c = tid & 63;
    if (node >= n) return;

    const float* xr = x + node * F_IN;
    float acc = 0.f;
#pragma unroll
    for (int k = 0; k < F_IN; k++) acc += xr[k] * sW[k * F1 + c];
    g_h1[node * F1 + c] = acc;

    float as = acc * sS[c], ad = acc * sD[c];
#pragma unroll
    for (int m = 1; m < 8; m <<= 1) {
        as += __shfl_xor_sync(0xffffffffu, as, m, 8);
        ad += __shfl_xor_sync(0xffffffffu, ad, m, 8);
    }
    if ((c & 7) == 0) {
        int j = node * HEADS + (c >> 3);
        g_as1[j] = as;
        g_ad1[j] = ad;
    }
}

// ------------------------- layer 1: dst-centric gather + normalize+ELU -----
// 8 threads per node, one per head; each owns its head's 8 features in regs.
__global__ void __launch_bounds__(256) k_gather1(const float* __restrict__ b1, int n) {
    int tid = threadIdx.x;
    int node = blockIdx.x * 32 + (tid >> 3);
    int h = tid & 7;
    if (node >= n) return;

    int beg = g_off[node], end = g_off[node + 1];
    float ad = g_ad1[node * 8 + h];

    // self-loop
    float wl = __expf(lrelu(g_as1[node * 8 + h] + ad));
    float4 a0 = *(const float4*)(g_h1 + node * F1 + h * 8);
    float4 a1 = *(const float4*)(g_h1 + node * F1 + h * 8 + 4);
    float4 acc0 = make_float4(a0.x*wl, a0.y*wl, a0.z*wl, a0.w*wl);
    float4 acc1 = make_float4(a1.x*wl, a1.y*wl, a1.z*wl, a1.w*wl);
    float ws = wl;

    int s_next = (beg < end) ? g_ssrc[beg] : 0;
    for (int j = beg; j < end; j++) {
        int s = s_next;
        if (j + 1 < end) s_next = g_ssrc[j + 1];
        float w = __expf(lrelu(g_as1[s * 8 + h] + ad));
        float4 v0 = *(const float4*)(g_h1 + s * F1 + h * 8);
        float4 v1 = *(const float4*)(g_h1 + s * F1 + h * 8 + 4);
        acc0.x += v0.x * w; acc0.y += v0.y * w; acc0.z += v0.z * w; acc0.w += v0.w * w;
        acc1.x += v1.x * w; acc1.y += v1.y * w; acc1.z += v1.z * w; acc1.w += v1.w * w;
        ws += w;
    }

    float r = __fdividef(1.f, ws);
    float4 bb0 = *(const float4*)(b1 + h * 8);
    float4 bb1 = *(const float4*)(b1 + h * 8 + 4);
    float4 o0, o1;
    o0.x = acc0.x * r + bb0.x; o0.x = o0.x > 0.f ? o0.x : expm1f(o0.x);
    o0.y = acc0.y * r + bb0.y; o0.y = o0.y > 0.f ? o0.y : expm1f(o0.y);
    o0.z = acc0.z * r + bb0.z; o0.z = o0.z > 0.f ? o0.z : expm1f(o0.z);
    o0.w = acc0.w * r + bb0.w; o0.w = o0.w > 0.f ? o0.w : expm1f(o0.w);
    o1.x = acc1.x * r + bb1.x; o1.x = o1.x > 0.f ? o1.x : expm1f(o1.x);
    o1.y = acc1.y * r + bb1.y; o1.y = o1.y > 0.f ? o1.y : expm1f(o1.y);
    o1.z = acc1.z * r + bb1.z; o1.z = o1.z > 0.f ? o1.z : expm1f(o1.z);
    o1.w = acc1.w * r + bb1.w; o1.w = o1.w > 0.f ? o1.w : expm1f(o1.w);
    *(float4*)(g_hL2 + node * F1 + h * 8)     = o0;
    *(float4*)(g_hL2 + node * F1 + h * 8 + 4) = o1;
}

// ------------------------- layer 2: gemm + logits ---------------------------
__global__ void __launch_bounds__(256) k_l2(const float* __restrict__ W2,
                                            const float* __restrict__ asrc,
                                            const float* __restrict__ adst, int n) {
    __shared__ float sW[F1 * DIM], sS[DIM], sD[DIM];
    int tid = threadIdx.x;
    for (int i = tid; i < F1 * DIM; i += 256) sW[i] = W2[i];
    if (tid < DIM) { sS[tid] = asrc[tid]; sD[tid] = adst[tid]; }
    __syncthreads();

    int nidx = blockIdx.x * blockDim.x + tid;
    if (nidx >= n) return;

    float acc[DIM] = {0.f,0.f,0.f,0.f,0.f,0.f,0.f,0.f};
    const float* row = g_hL2 + nidx * F1;
#pragma unroll
    for (int k = 0; k < F1; k += 4) {
        float4 t = *(const float4*)(row + k);
#pragma unroll
        for (int c = 0; c < DIM; c++)
            acc[c] += t.x * sW[k * 8 + c] + t.y * sW[(k + 1) * 8 + c]
                    + t.z * sW[(k + 2) * 8 + c] + t.w * sW[(k + 3) * 8 + c];
    }
    float as = 0.f, ad = 0.f;
#pragma unroll
    for (int c = 0; c < DIM; c++) {
        as += acc[c] * sS[c];
        ad += acc[c] * sD[c];
        g_h2[nidx * DIM + c] = acc[c];
    }
    g_as2[nidx] = as;
    g_ad2[nidx] = ad;
}

// ------------------------- layer 2: dst-centric gather + finalize ----------
// 8 threads per node, one per output column.
__global__ void __launch_bounds__(256) k_gather2(const float* __restrict__ b2,
                                                 int n, float* __restrict__ out) {
    int tid = threadIdx.x;
    int node = blockIdx.x * 32 + (tid >> 3);
    int c = tid & 7;
    if (node >= n) return;

    int beg = g_off[node], end = g_off[node + 1];
    float ad = g_ad2[node];

    float wl = __expf(lrelu(g_as2[node] + ad));
    float acc = g_h2[node * DIM + c] * wl;
    float ws = wl;

    int s_next = (beg < end) ? g_ssrc[beg] : 0;
    for (int j = beg; j < end; j++) {
        int s = s_next;
        if (j + 1 < end) s_next = g_ssrc[j + 1];
        float w = __expf(lrelu(g_as2[s] + ad));
        acc += w * g_h2[s * DIM + c];
        ws += w;
    }
    out[node * DIM + c] = acc * __fdividef(1.f, ws) + __ldg(&b2[c]);
}

// ------------------------- launch -----------------------------------------
extern "C" void kernel_launch(void* const* d_in, const int* in_sizes, int n_in,
                              void* d_out, int out_size) {
    const float* x   = (const float*)d_in[0];
    const void*  ei  = d_in[1];
    const float* W1  = (const float*)d_in[2];
    const float* as1 = (const float*)d_in[3];
    const float* ad1 = (const float*)d_in[4];
    const float* b1  = (const float*)d_in[5];
    const float* W2  = (const float*)d_in[6];
    const float* as2 = (const float*)d_in[7];
    const float* ad2 = (const float*)d_in[8];
    const float* b2  = (const float*)d_in[9];
    float* out = (float*)d_out;

    int n = in_sizes[0] / F_IN;
    int e = in_sizes[1] / 2;
    const int B = 256;
    auto g = [&](long long t) { return (unsigned)((t + B - 1) / B); };

    // CSR build (recomputed every launch; deterministic work, graph-capturable)
    k_detect <<<1, 32>>>((const unsigned long long*)ei);
    k_zero   <<<g(n), B>>>(n);
    k_convert<<<g(e), B>>>(ei, e);
    k_scan   <<<1, 1024>>>(n, e);
    k_scatter<<<g(e), B>>>(e);

    // layer 1
    k_l1     <<<(n + 3) / 4, B>>>(x, W1, as1, ad1, n);
    k_gather1<<<(n + 31) / 32, B>>>(b1, n);

    // layer 2
    k_l2     <<<g(n), B>>>(W2, as2, ad2, n);
    k_gather2<<<(n + 31) / 32, B>>>(b2, n, out);
}

// round 7
// speedup vs baseline: 1.8903x; 1.8903x over previous
#include <cuda_runtime.h>

#define F_IN  14
#define HEADS 8
#define DIM   8
#define F1    64          // HEADS*DIM
#define NEG   0.2f
#define MAXN  100000
#define MAXE  1600000
#define TILE  1024
#define MAXT  ((MAXN + TILE - 1) / TILE)

// ------------------------- scratch (device globals; no allocs) -------------
__device__ float g_h1  [MAXN * F1];     // layer1 linear output [N,64]
__device__ float g_hL2 [MAXN * F1];     // layer1 final output (ELU'd) = layer2 input
__device__ float g_as1 [MAXN * HEADS];
__device__ float g_ad1 [MAXN * HEADS];
__device__ float g_h2  [MAXN * DIM];    // layer2 linear output [N,8]
__device__ float g_as2 [MAXN];
__device__ float g_ad2 [MAXN];
__device__ int   g_src [MAXE];
__device__ int   g_dst [MAXE];
__device__ int   g_ssrc[MAXE];          // src ids sorted by dst (CSR col idx)
__device__ int   g_cnt [MAXN];          // in-degree histogram
__device__ int   g_off [MAXN + 1];      // CSR row offsets
__device__ int   g_cur [MAXN];          // scatter cursors
__device__ int   g_bsum[MAXT];          // per-tile sums
__device__ int   g_bpre[MAXT];          // per-tile exclusive prefixes
__device__ int   g_is64;

// ------------------------- helpers ----------------------------------------
__device__ __forceinline__ float lrelu(float x) { return x > 0.f ? x : NEG * x; }

// ------------------------- edge dtype detect -------------------------------
__global__ void k_detect(const unsigned long long* p) {
    if (threadIdx.x == 0) {
        int is64 = 1;
        for (int i = 0; i < 64; i++)
            if (p[i] >> 32) { is64 = 0; break; }
        g_is64 = is64;
    }
}

__global__ void k_zero(int n) {
    int i = blockIdx.x * blockDim.x + threadIdx.x;
    if (i < n) g_cnt[i] = 0;
}

// convert indices to int32 + build dst histogram
__global__ void k_convert(const void* ei, int e) {
    int i = blockIdx.x * blockDim.x + threadIdx.x;
    if (i >= e) return;
    int s, d;
    if (g_is64) {
        const long long* p = (const long long*)ei;
        s = (int)p[i]; d = (int)p[e + i];
    } else {
        const int* p = (const int*)ei;
        s = p[i]; d = p[e + i];
    }
    g_src[i] = s;
    g_dst[i] = d;
    atomicAdd(&g_cnt[d], 1);
}

// ---- hierarchical scan: tile sums -> tiny scan -> per-tile offsets --------
__global__ void __launch_bounds__(256) k_tilesum(int n) {
    __shared__ int sw[8];
    int base = blockIdx.x * TILE;
    int t = threadIdx.x;
    int s = 0;
#pragma unroll
    for (int k = 0; k < 4; k++) {
        int i = base + t * 4 + k;
        if (i < n) s += g_cnt[i];
    }
#pragma unroll
    for (int m = 16; m; m >>= 1) s += __shfl_xor_sync(0xffffffffu, s, m);
    if ((t & 31) == 0) sw[t >> 5] = s;
    __syncthreads();
    if (t == 0) {
        int tot = 0;
#pragma unroll
        for (int w = 0; w < 8; w++) tot += sw[w];
        g_bsum[blockIdx.x] = tot;
    }
}

__global__ void __launch_bounds__(128) k_scanb(int ntiles, int n, int e) {
    __shared__ int sp[128];
    int t = threadIdx.x;
    int v = (t < ntiles) ? g_bsum[t] : 0;
    sp[t] = v;
    __syncthreads();
#pragma unroll
    for (int off = 1; off < 128; off <<= 1) {
        int u = (t >= off) ? sp[t - off] : 0;
        __syncthreads();
        sp[t] += u;
        __syncthreads();
    }
    if (t < ntiles) g_bpre[t] = sp[t] - v;     // exclusive prefix
    if (t == 0) g_off[n] = e;
}

__global__ void __launch_bounds__(256) k_offsets(int n) {
    __shared__ int sp[256];
    int base = blockIdx.x * TILE;
    int t = threadIdx.x;
    int v[4]; int s = 0;
#pragma unroll
    for (int k = 0; k < 4; k++) {
        int i = base + t * 4 + k;
        v[k] = (i < n) ? g_cnt[i] : 0;
        s += v[k];
    }
    sp[t] = s;
    __syncthreads();
#pragma unroll
    for (int off = 1; off < 256; off <<= 1) {
        int u = (t >= off) ? sp[t - off] : 0;
        __syncthreads();
        sp[t] += u;
        __syncthreads();
    }
    int run = g_bpre[blockIdx.x] + sp[t] - s;  // exclusive within block + tile prefix
#pragma unroll
    for (int k = 0; k < 4; k++) {
        int i = base + t * 4 + k;
        if (i < n) { g_off[i] = run; g_cur[i] = run; run += v[k]; }
    }
}

__global__ void k_scatter(int e) {
    int i = blockIdx.x * blockDim.x + threadIdx.x;
    if (i >= e) return;
    int d = g_dst[i];
    int pos = atomicAdd(&g_cur[d], 1);
    g_ssrc[pos] = g_src[i];
}

// ------------------------- layer 1: fused gemm + logits --------------------
__global__ void __launch_bounds__(256) k_l1(const float* __restrict__ x,
                                            const float* __restrict__ W1,
                                            const float* __restrict__ asrc,
                                            const float* __restrict__ adst, int n) {
    __shared__ float sW[F_IN * F1];
    __shared__ float sS[F1], sD[F1];
    int tid = threadIdx.x;
    for (int i = tid; i < F_IN * F1; i += 256) sW[i] = W1[i];
    if (tid < F1) { sS[tid] = asrc[tid]; sD[tid] = adst[tid]; }
    __syncthreads();

    int node = blockIdx.x * 4 + (tid >> 6);
    int c = tid & 63;
    if (node >= n) return;

    const float* xr = x + node * F_IN;
    float acc = 0.f;
#pragma unroll
    for (int k = 0; k < F_IN; k++) acc += xr[k] * sW[k * F1 + c];
    g_h1[node * F1 + c] = acc;

    float as = acc * sS[c], ad = acc * sD[c];
#pragma unroll
    for (int m = 1; m < 8; m <<= 1) {
        as += __shfl_xor_sync(0xffffffffu, as, m, 8);
        ad += __shfl_xor_sync(0xffffffffu, ad, m, 8);
    }
    if ((c & 7) == 0) {
        int j = node * HEADS + (c >> 3);
        g_as1[j] = as;
        g_ad1[j] = ad;
    }
}

// ------------------------- layer 1: dst-centric gather + normalize+ELU -----
__global__ void __launch_bounds__(256) k_gather1(const float* __restrict__ b1, int n) {
    int tid = threadIdx.x;
    int node = blockIdx.x * 32 + (tid >> 3);
    int h = tid & 7;
    if (node >= n) return;

    int beg = g_off[node], end = g_off[node + 1];
    float ad = g_ad1[node * 8 + h];

    float wl = __expf(lrelu(g_as1[node * 8 + h] + ad));
    float4 a0 = *(const float4*)(g_h1 + node * F1 + h * 8);
    float4 a1 = *(const float4*)(g_h1 + node * F1 + h * 8 + 4);
    float4 acc0 = make_float4(a0.x*wl, a0.y*wl, a0.z*wl, a0.w*wl);
    float4 acc1 = make_float4(a1.x*wl, a1.y*wl, a1.z*wl, a1.w*wl);
    float ws = wl;

    int s_next = (beg < end) ? g_ssrc[beg] : 0;
    for (int j = beg; j < end; j++) {
        int s = s_next;
        if (j + 1 < end) s_next = g_ssrc[j + 1];
        float w = __expf(lrelu(g_as1[s * 8 + h] + ad));
        float4 v0 = *(const float4*)(g_h1 + s * F1 + h * 8);
        float4 v1 = *(const float4*)(g_h1 + s * F1 + h * 8 + 4);
        acc0.x += v0.x * w; acc0.y += v0.y * w; acc0.z += v0.z * w; acc0.w += v0.w * w;
        acc1.x += v1.x * w; acc1.y += v1.y * w; acc1.z += v1.z * w; acc1.w += v1.w * w;
        ws += w;
    }

    float r = __fdividef(1.f, ws);
    float4 bb0 = *(const float4*)(b1 + h * 8);
    float4 bb1 = *(const float4*)(b1 + h * 8 + 4);
    float4 o0, o1;
    o0.x = acc0.x * r + bb0.x; o0.x = o0.x > 0.f ? o0.x : expm1f(o0.x);
    o0.y = acc0.y * r + bb0.y; o0.y = o0.y > 0.f ? o0.y : expm1f(o0.y);
    o0.z = acc0.z * r + bb0.z; o0.z = o0.z > 0.f ? o0.z : expm1f(o0.z);
    o0.w = acc0.w * r + bb0.w; o0.w = o0.w > 0.f ? o0.w : expm1f(o0.w);
    o1.x = acc1.x * r + bb1.x; o1.x = o1.x > 0.f ? o1.x : expm1f(o1.x);
    o1.y = acc1.y * r + bb1.y; o1.y = o1.y > 0.f ? o1.y : expm1f(o1.y);
    o1.z = acc1.z * r + bb1.z; o1.z = o1.z > 0.f ? o1.z : expm1f(o1.z);
    o1.w = acc1.w * r + bb1.w; o1.w = o1.w > 0.f ? o1.w : expm1f(o1.w);
    *(float4*)(g_hL2 + node * F1 + h * 8)     = o0;
    *(float4*)(g_hL2 + node * F1 + h * 8 + 4) = o1;
}

// ------------------------- layer 2: gemm + logits ---------------------------
__global__ void __launch_bounds__(256) k_l2(const float* __restrict__ W2,
                                            const float* __restrict__ asrc,
                                            const float* __restrict__ adst, int n) {
    __shared__ float sW[F1 * DIM], sS[DIM], sD[DIM];
    int tid = threadIdx.x;
    for (int i = tid; i < F1 * DIM; i += 256) sW[i] = W2[i];
    if (tid < DIM) { sS[tid] = asrc[tid]; sD[tid] = adst[tid]; }
    __syncthreads();

    int nidx = blockIdx.x * blockDim.x + tid;
    if (nidx >= n) return;

    float acc[DIM] = {0.f,0.f,0.f,0.f,0.f,0.f,0.f,0.f};
    const float* row = g_hL2 + nidx * F1;
#pragma unroll
    for (int k = 0; k < F1; k += 4) {
        float4 t = *(const float4*)(row + k);
#pragma unroll
        for (int c = 0; c < DIM; c++)
            acc[c] += t.x * sW[k * 8 + c] + t.y * sW[(k + 1) * 8 + c]
                    + t.z * sW[(k + 2) * 8 + c] + t.w * sW[(k + 3) * 8 + c];
    }
    float as = 0.f, ad = 0.f;
#pragma unroll
    for (int c = 0; c < DIM; c++) {
        as += acc[c] * sS[c];
        ad += acc[c] * sD[c];
        g_h2[nidx * DIM + c] = acc[c];
    }
    g_as2[nidx] = as;
    g_ad2[nidx] = ad;
}

// ------------------------- layer 2: dst-centric gather + finalize ----------
__global__ void __launch_bounds__(256) k_gather2(const float* __restrict__ b2,
                                                 int n, float* __restrict__ out) {
    int tid = threadIdx.x;
    int node = blockIdx.x * 32 + (tid >> 3);
    int c = tid & 7;
    if (node >= n) return;

    int beg = g_off[node], end = g_off[node + 1];
    float ad = g_ad2[node];

    float wl = __expf(lrelu(g_as2[node] + ad));
    float acc = g_h2[node * DIM + c] * wl;
    float ws = wl;

    int s_next = (beg < end) ? g_ssrc[beg] : 0;
    for (int j = beg; j < end; j++) {
        int s = s_next;
        if (j + 1 < end) s_next = g_ssrc[j + 1];
        float w = __expf(lrelu(g_as2[s] + ad));
        acc += w * g_h2[s * DIM + c];
        ws += w;
    }
    out[node * DIM + c] = acc * __fdividef(1.f, ws) + __ldg(&b2[c]);
}

// ------------------------- launch -----------------------------------------
extern "C" void kernel_launch(void* const* d_in, const int* in_sizes, int n_in,
                              void* d_out, int out_size) {
    const float* x   = (const float*)d_in[0];
    const void*  ei  = d_in[1];
    const float* W1  = (const float*)d_in[2];
    const float* as1 = (const float*)d_in[3];
    const float* ad1 = (const float*)d_in[4];
    const float* b1  = (const float*)d_in[5];
    const float* W2  = (const float*)d_in[6];
    const float* as2 = (const float*)d_in[7];
    const float* ad2 = (const float*)d_in[8];
    const float* b2  = (const float*)d_in[9];
    float* out = (float*)d_out;

    int n = in_sizes[0] / F_IN;
    int e = in_sizes[1] / 2;
    const int B = 256;
    auto g = [&](long long t) { return (unsigned)((t + B - 1) / B); };
    int ntiles = (n + TILE - 1) / TILE;

    // CSR build
    k_detect  <<<1, 32>>>((const unsigned long long*)ei);
    k_zero    <<<g(n), B>>>(n);
    k_convert <<<g(e), B>>>(ei, e);
    k_tilesum <<<ntiles, B>>>(n);
    k_scanb   <<<1, 128>>>(ntiles, n, e);
    k_offsets <<<ntiles, B>>>(n);
    k_scatter <<<g(e), B>>>(e);

    // layer 1
    k_l1      <<<(n + 3) / 4, B>>>(x, W1, as1, ad1, n);
    k_gather1 <<<(n + 31) / 32, B>>>(b1, n);

    // layer 2
    k_l2      <<<g(n), B>>>(W2, as2, ad2, n);
    k_gather2 <<<(n + 31) / 32, B>>>(b2, n, out);
}